// round 9
// baseline (speedup 1.0000x reference)
#include <cuda_runtime.h>

#define NBLK 24
#define BATCH 256
#define CH 32
#define TQ 256
#define TQO 257

#define NROWS   (NBLK * BATCH * CH)         // 196608 rows
#define NELEM   (NROWS * TQ)                // 50,331,648 floats to copy

#define COPY_CTAS   1024
#define COPY_TPB    256
#define COPY_UNROLL 8
#define COPY_ITERS  (NELEM / (COPY_CTAS * COPY_TPB * COPY_UNROLL))  // 24 exactly

#define CMP_CTAS 16
#define CMP_TPB  512

// XOR swizzle: row pitch 32 floats, 16B chunks swizzled by row so that
// float4 LDS from rows (lane mod 8 distinct) start at distinct banks.
#define SWZ(r, c) ((((r) << 5)) + (((((c) >> 2) ^ ((r) & 7)) << 2)) + ((c) & 3))

// ---------------------------------------------------------------------------
// Copy kernel: queues(…,256) -> new_queues(…,257)[0:256].
// dst linear index = idx + (idx >> 8). Zero smem, batched loads, streaming.
// ---------------------------------------------------------------------------
__global__ void __launch_bounds__(COPY_TPB) queue_copy_kernel(
    const float* __restrict__ src, float* __restrict__ dst)
{
    const unsigned stride = COPY_CTAS * COPY_TPB;           // 262144
    unsigned base = blockIdx.x * COPY_TPB + threadIdx.x;
#pragma unroll 1
    for (int it = 0; it < COPY_ITERS; it++) {
        float v[COPY_UNROLL];
#pragma unroll
        for (int j = 0; j < COPY_UNROLL; j++)
            v[j] = __ldcs(src + base + j * stride);
#pragma unroll
        for (int j = 0; j < COPY_UNROLL; j++) {
            const unsigned idx = base + j * stride;
            __stcs(dst + idx + (idx >> 8), v[j]);
        }
        base += COPY_UNROLL * stride;
    }
}

// ---------------------------------------------------------------------------
// Compute kernel: recurrent 24-block chain, warp-per-batch, 16 warps/CTA.
// Software-pipelined: weights for block i+1 prefetched into registers while
// block i computes from shared; one staging round + 2 barriers per iter.
// ---------------------------------------------------------------------------
__global__ void __launch_bounds__(CMP_TPB) wave_compute_kernel(
    const float* __restrict__ queues,
    const float* __restrict__ x,
    const float* __restrict__ num,
    const int*   __restrict__ cat,
    const float* __restrict__ emb,
    const float* __restrict__ W_in,
    const float* __restrict__ b_in,
    const float* __restrict__ W_conv,   // (24,64,32,2)
    const float* __restrict__ b_conv,   // (24,64)
    const float* __restrict__ W_res,    // (24,32,32)
    const float* __restrict__ b_res,
    const float* __restrict__ W_skip,   // (24,32,32)
    const float* __restrict__ b_skip,
    const float* __restrict__ W_o1,     // (128,768)
    const float* __restrict__ b_o1,
    const float* __restrict__ W_o2,
    const float* __restrict__ b_o2,
    float* __restrict__ out)
{
    __shared__ __align__(16) float s_wc0[64 * 32];   // swizzled [o][c] k=0
    __shared__ __align__(16) float s_wc1[64 * 32];   // swizzled [o][c] k=1
    __shared__ __align__(16) float s_wrs[32 * 32];   // swizzled [o][c]
    __shared__ __align__(16) float s_wsk[32 * 32];   // swizzled [o][c]
    __shared__ __align__(16) float s_wo1[128 * 32];  // swizzled [h][s]
    __shared__ __align__(16) float s_tap[16][32];
    __shared__ __align__(16) float s_cur[16][32];
    __shared__ __align__(16) float s_g[16][32];

    float* __restrict__ nq = out + BATCH;

    const int tid  = threadIdx.x;
    const int w    = tid >> 5;
    const int lane = tid & 31;
    const int b    = blockIdx.x * 16 + w;

    // ---- prefetch block-0 weights into registers (overlaps input proj) ----
    float2 pf_wc[4];
    float  pf_wrs[2], pf_wsk[2], pf_wo1[8];
    {
        const float2* __restrict__ Wc2 = (const float2*)W_conv;
#pragma unroll
        for (int j = 0; j < 4; j++) pf_wc[j] = Wc2[tid + j * 512];
#pragma unroll
        for (int j = 0; j < 2; j++) {
            pf_wrs[j] = W_res [tid + j * 512];
            pf_wsk[j] = W_skip[tid + j * 512];
        }
#pragma unroll
        for (int j = 0; j < 8; j++) {
            const int idx = tid + j * 512;
            pf_wo1[j] = W_o1[(idx >> 5) * 768 + (idx & 31)];
        }
    }
    float zb0  = b_conv[lane];
    float zb1  = b_conv[32 + lane];
    float rb   = b_res [lane];
    float sb   = b_skip[lane];
    float tapc = queues[((size_t)b * CH + lane) * TQ + (TQ - 1)];  // d=1 at i=0

    // ---- input projection ------------------------------------------------
    if (lane < 25) {
        float v;
        if (lane == 0)      v = x[b];
        else if (lane < 9)  v = num[b * 8 + (lane - 1)];
        else                v = emb[cat[b] * 16 + (lane - 9)];
        s_g[w][lane] = v;
    }
    __syncwarp();
    float cur = b_in[lane];
#pragma unroll
    for (int k = 0; k < 25; k++)
        cur += W_in[lane * 25 + k] * s_g[w][k];
    __syncwarp();

    // ---- stage block-0 weights into shared -------------------------------
#pragma unroll
    for (int j = 0; j < 4; j++) {
        const int idx = tid + j * 512;
        const int o = idx >> 5, c = idx & 31;
        s_wc0[SWZ(o, c)] = pf_wc[j].x;
        s_wc1[SWZ(o, c)] = pf_wc[j].y;
    }
#pragma unroll
    for (int j = 0; j < 2; j++) {
        const int idx = tid + j * 512;
        const int o = idx >> 5, c = idx & 31;
        s_wrs[SWZ(o, c)] = pf_wrs[j];
        s_wsk[SWZ(o, c)] = pf_wsk[j];
    }
#pragma unroll
    for (int j = 0; j < 8; j++) {
        const int idx = tid + j * 512;
        const int h = idx >> 5, s = idx & 31;
        s_wo1[SWZ(h, s)] = pf_wo1[j];
    }
    __syncthreads();

    float acc0 = 0.f, acc1 = 0.f, acc2 = 0.f, acc3 = 0.f;

#pragma unroll 1
    for (int i = 0; i < NBLK; i++) {
        // ---- prefetch block i+1 (independent of recurrence) --------------
        float zb0n, zb1n, rbn, sbn, tapn;
        if (i < NBLK - 1) {
            const int in = i + 1;
            const float2* __restrict__ Wc2 = (const float2*)(W_conv + in * 4096);
#pragma unroll
            for (int j = 0; j < 4; j++) pf_wc[j] = Wc2[tid + j * 512];
#pragma unroll
            for (int j = 0; j < 2; j++) {
                pf_wrs[j] = W_res [in * 1024 + tid + j * 512];
                pf_wsk[j] = W_skip[in * 1024 + tid + j * 512];
            }
#pragma unroll
            for (int j = 0; j < 8; j++) {
                const int idx = tid + j * 512;
                pf_wo1[j] = W_o1[(idx >> 5) * 768 + in * 32 + (idx & 31)];
            }
            zb0n = b_conv[in * 64 + lane];
            zb1n = b_conv[in * 64 + 32 + lane];
            rbn  = b_res [in * 32 + lane];
            sbn  = b_skip[in * 32 + lane];
            const int dn = 1 << (in & 7);
            tapn = queues[((size_t)(in * BATCH + b) * CH + lane) * TQ + (TQ - dn)];
        }

        // ---- compute block i from shared ---------------------------------
        const size_t rowbase = (size_t)(i * BATCH + b) * CH + lane;
        nq[rowbase * TQO + TQ] = cur;   // appended element: cur entering block i
        s_tap[w][lane] = tapc;
        s_cur[w][lane] = cur;
        __syncwarp();

        float z0a = zb0, z0b = 0.f, z1a = zb1, z1b = 0.f;
#pragma unroll
        for (int c = 0; c < 32; c += 4) {
            const float4 a   = *(const float4*)&s_tap[w][c];
            const float4 u   = *(const float4*)&s_cur[w][c];
            const float4 w00 = *(const float4*)&s_wc0[SWZ(lane, c)];
            const float4 w10 = *(const float4*)&s_wc1[SWZ(lane, c)];
            const float4 w01 = *(const float4*)&s_wc0[SWZ(lane + 32, c)];
            const float4 w11 = *(const float4*)&s_wc1[SWZ(lane + 32, c)];
            z0a += a.x * w00.x + a.y * w00.y + a.z * w00.z + a.w * w00.w;
            z0b += u.x * w10.x + u.y * w10.y + u.z * w10.z + u.w * w10.w;
            z1a += a.x * w01.x + a.y * w01.y + a.z * w01.z + a.w * w01.w;
            z1b += u.x * w11.x + u.y * w11.y + u.z * w11.z + u.w * w11.w;
        }

        const float z1s = z1a + z1b;
        const float gated = tanhf(z0a + z0b) * (1.f / (1.f + __expf(-z1s)));
        s_g[w][lane] = gated;
        __syncwarp();

        float sk = sb, rs = rb;
#pragma unroll
        for (int c = 0; c < 32; c += 4) {
            const float4 g  = *(const float4*)&s_g[w][c];
            const float4 wr = *(const float4*)&s_wrs[SWZ(lane, c)];
            const float4 ws = *(const float4*)&s_wsk[SWZ(lane, c)];
            rs += g.x * wr.x + g.y * wr.y + g.z * wr.z + g.w * wr.w;
            sk += g.x * ws.x + g.y * ws.y + g.z * ws.z + g.w * ws.w;
        }
        cur = rs + cur;  // + tap1 (= old cur)

        s_tap[w][lane] = fmaxf(sk, 0.f);
        __syncwarp();

#pragma unroll
        for (int s = 0; s < 32; s += 4) {
            const float4 sr = *(const float4*)&s_tap[w][s];
            const float4 v0 = *(const float4*)&s_wo1[SWZ(lane,      s)];
            const float4 v1 = *(const float4*)&s_wo1[SWZ(lane + 32, s)];
            const float4 v2 = *(const float4*)&s_wo1[SWZ(lane + 64, s)];
            const float4 v3 = *(const float4*)&s_wo1[SWZ(lane + 96, s)];
            acc0 += sr.x * v0.x + sr.y * v0.y + sr.z * v0.z + sr.w * v0.w;
            acc1 += sr.x * v1.x + sr.y * v1.y + sr.z * v1.z + sr.w * v1.w;
            acc2 += sr.x * v2.x + sr.y * v2.y + sr.z * v2.z + sr.w * v2.w;
            acc3 += sr.x * v3.x + sr.y * v3.y + sr.z * v3.z + sr.w * v3.w;
        }
        __syncwarp();

        // ---- rotate staged weights ---------------------------------------
        __syncthreads();                 // all warps done reading shared
        if (i < NBLK - 1) {
#pragma unroll
            for (int j = 0; j < 4; j++) {
                const int idx = tid + j * 512;
                const int o = idx >> 5, c = idx & 31;
                s_wc0[SWZ(o, c)] = pf_wc[j].x;
                s_wc1[SWZ(o, c)] = pf_wc[j].y;
            }
#pragma unroll
            for (int j = 0; j < 2; j++) {
                const int idx = tid + j * 512;
                const int o = idx >> 5, c = idx & 31;
                s_wrs[SWZ(o, c)] = pf_wrs[j];
                s_wsk[SWZ(o, c)] = pf_wsk[j];
            }
#pragma unroll
            for (int j = 0; j < 8; j++) {
                const int idx = tid + j * 512;
                const int h = idx >> 5, s = idx & 31;
                s_wo1[SWZ(h, s)] = pf_wo1[j];
            }
            zb0 = zb0n; zb1 = zb1n; rb = rbn; sb = sbn; tapc = tapn;
            __syncthreads();             // staged writes visible
        }
    }

    // ---- output head -----------------------------------------------------
    float p = 0.f;
    p += fmaxf(acc0 + b_o1[lane      ], 0.f) * W_o2[lane      ];
    p += fmaxf(acc1 + b_o1[lane + 32 ], 0.f) * W_o2[lane + 32 ];
    p += fmaxf(acc2 + b_o1[lane + 64 ], 0.f) * W_o2[lane + 64 ];
    p += fmaxf(acc3 + b_o1[lane + 96 ], 0.f) * W_o2[lane + 96 ];
#pragma unroll
    for (int off = 16; off; off >>= 1)
        p += __shfl_xor_sync(0xffffffffu, p, off);
    if (lane == 0)
        out[b] = p + b_o2[0];
}

extern "C" void kernel_launch(void* const* d_in, const int* in_sizes, int n_in,
                              void* d_out, int out_size) {
    const float* queues = (const float*)d_in[0];
    const float* x      = (const float*)d_in[1];
    const float* num    = (const float*)d_in[2];
    const int*   cat    = (const int*)  d_in[3];
    const float* emb    = (const float*)d_in[4];
    const float* W_in   = (const float*)d_in[5];
    const float* b_in   = (const float*)d_in[6];
    const float* W_conv = (const float*)d_in[7];
    const float* b_conv = (const float*)d_in[8];
    const float* W_res  = (const float*)d_in[9];
    const float* b_res  = (const float*)d_in[10];
    const float* W_skip = (const float*)d_in[11];
    const float* b_skip = (const float*)d_in[12];
    const float* W_o1   = (const float*)d_in[13];
    const float* b_o1   = (const float*)d_in[14];
    const float* W_o2   = (const float*)d_in[15];
    const float* b_o2   = (const float*)d_in[16];
    float* out = (float*)d_out;
    float* nq  = out + BATCH;

    static cudaStream_t s2 = nullptr;
    static cudaEvent_t  e_fork = nullptr, e_join = nullptr;
    if (s2 == nullptr) {
        cudaStreamCreateWithFlags(&s2, cudaStreamNonBlocking);
        cudaEventCreateWithFlags(&e_fork, cudaEventDisableTiming);
        cudaEventCreateWithFlags(&e_join, cudaEventDisableTiming);
    }

    cudaEventRecord(e_fork, 0);
    cudaStreamWaitEvent(s2, e_fork, 0);

    queue_copy_kernel<<<COPY_CTAS, COPY_TPB, 0, s2>>>(queues, nq);

    wave_compute_kernel<<<CMP_CTAS, CMP_TPB>>>(
        queues, x, num, cat, emb, W_in, b_in, W_conv, b_conv,
        W_res, b_res, W_skip, b_skip, W_o1, b_o1, W_o2, b_o2, out);

    cudaEventRecord(e_join, s2);
    cudaStreamWaitEvent(0, e_join, 0);
}

// round 11
// speedup vs baseline: 1.3127x; 1.3127x over previous
#include <cuda_runtime.h>
#include <cstdint>

#define NBLK 24
#define BATCH 256
#define CH 32
#define TQ 256
#define TQO 257

#define NROWS   (NBLK * BATCH * CH)
#define NELEM   (NROWS * TQ)                // 50,331,648 floats

#define COPY_CTAS   768
#define COPY_TPB    256
#define COPY_UNROLL 8
#define COPY_ITERS  (NELEM / (COPY_CTAS * COPY_TPB * COPY_UNROLL))  // 32 exactly

#define CMP_CTAS 64
#define CMP_TPB  128

// Dynamic smem layout (float offsets)
#define WC_OFF   0              // [2][4096]  W_conv interleaved (o,c,k), swizzled
#define WRS_OFF  8192           // [2][1024]
#define WSK_OFF  10240          // [2][1024]
#define WO1_OFF  12288          // [2][4096]
#define ACT_OFF  20480          // tap[4][32] | cur[4][32] | g[4][32]
#define SMEM_FLOATS (ACT_OFF + 384)
#define SMEM_BYTES  (SMEM_FLOATS * 4)       // 83456 B

// Swizzles: XOR 16B-chunk index with (row & 7) -> conflict-free per 8-lane phase.
#define SWZ16(o, p) (((o) << 6) + ((((p) ^ ((o) & 7)) << 2)))   // 64-float rows
#define SWZ8(r, q)  (((r) << 5) + ((((q) ^ ((r) & 7)) << 2)))   // 32-float rows

__device__ __forceinline__ void cpa16(unsigned int dst_smem, const void* src) {
    asm volatile("cp.async.cg.shared.global [%0], [%1], 16;\n"
                 :: "r"(dst_smem), "l"(src));
}
__device__ __forceinline__ void cpa_commit() {
    asm volatile("cp.async.commit_group;\n" ::: "memory");
}
__device__ __forceinline__ void cpa_wait0() {
    asm volatile("cp.async.wait_group 0;\n" ::: "memory");
}

// ---------------------------------------------------------------------------
// Copy kernel: queues(…,256) -> new_queues(…,257)[0:256].
// ---------------------------------------------------------------------------
__global__ void __launch_bounds__(COPY_TPB) queue_copy_kernel(
    const float* __restrict__ src, float* __restrict__ dst)
{
    const unsigned stride = COPY_CTAS * COPY_TPB;
    unsigned base = blockIdx.x * COPY_TPB + threadIdx.x;
#pragma unroll 1
    for (int it = 0; it < COPY_ITERS; it++) {
        float v[COPY_UNROLL];
#pragma unroll
        for (int j = 0; j < COPY_UNROLL; j++)
            v[j] = __ldcs(src + base + j * stride);
#pragma unroll
        for (int j = 0; j < COPY_UNROLL; j++) {
            const unsigned idx = base + j * stride;
            __stcs(dst + idx + (idx >> 8), v[j]);
        }
        base += COPY_UNROLL * stride;
    }
}

// ---------------------------------------------------------------------------
// Compute kernel: 64 CTAs x 4 warps (warp-per-batch), cp.async double-buffered
// weight staging, one __syncthreads per block-iteration.
// ---------------------------------------------------------------------------
__global__ void __launch_bounds__(CMP_TPB) wave_compute_kernel(
    const float* __restrict__ queues,
    const float* __restrict__ x,
    const float* __restrict__ num,
    const int*   __restrict__ cat,
    const float* __restrict__ emb,
    const float* __restrict__ W_in,
    const float* __restrict__ b_in,
    const float* __restrict__ W_conv,   // (24,64,32,2)
    const float* __restrict__ b_conv,
    const float* __restrict__ W_res,    // (24,32,32)
    const float* __restrict__ b_res,
    const float* __restrict__ W_skip,   // (24,32,32)
    const float* __restrict__ b_skip,
    const float* __restrict__ W_o1,     // (128,768)
    const float* __restrict__ b_o1,
    const float* __restrict__ W_o2,
    const float* __restrict__ b_o2,
    float* __restrict__ out)
{
    extern __shared__ __align__(16) float sm[];
    float* __restrict__ nq = out + BATCH;

    const int tid  = threadIdx.x;
    const int w    = tid >> 5;
    const int lane = tid & 31;
    const int b    = blockIdx.x * 4 + w;

    const unsigned int smem_u32 = (unsigned int)__cvta_generic_to_shared(sm);

    float* s_tap = sm + ACT_OFF       + w * 32;
    float* s_cur = sm + ACT_OFF + 128 + w * 32;
    float* s_g   = sm + ACT_OFF + 256 + w * 32;

    // ---- stage-issue helper (block blk -> buffer beta) --------------------
    auto issue_stage = [&](int blk, int beta) {
        // W_conv: 1024 chunks of 16B, interleaved (o, c-pair{k0,k1})
#pragma unroll
        for (int j = 0; j < 8; j++) {
            const int m = tid + j * 128;          // 0..1023
            const int o = m >> 4, ch = m & 15;
            cpa16(smem_u32 + (WC_OFF + beta * 4096 + SWZ16(o, ch)) * 4,
                  W_conv + (size_t)blk * 4096 + m * 4);
        }
        // W_res / W_skip: 256 chunks each
#pragma unroll
        for (int j = 0; j < 2; j++) {
            const int m = tid + j * 128;          // 0..255
            const int o = m >> 3, ch = m & 7;
            cpa16(smem_u32 + (WRS_OFF + beta * 1024 + SWZ8(o, ch)) * 4,
                  W_res + (size_t)blk * 1024 + m * 4);
            cpa16(smem_u32 + (WSK_OFF + beta * 1024 + SWZ8(o, ch)) * 4,
                  W_skip + (size_t)blk * 1024 + m * 4);
        }
        // W_o1 column slice: 1024 chunks
#pragma unroll
        for (int j = 0; j < 8; j++) {
            const int m = tid + j * 128;          // 0..1023
            const int h = m >> 3, ch = m & 7;
            cpa16(smem_u32 + (WO1_OFF + beta * 4096 + SWZ8(h, ch)) * 4,
                  W_o1 + (size_t)h * 768 + blk * 32 + ch * 4);
        }
        cpa_commit();
    };

    // ---- prologue: issue block 0, overlap with input projection -----------
    issue_stage(0, 0);

    float zb0  = b_conv[lane];
    float zb1  = b_conv[32 + lane];
    float rb   = b_res [lane];
    float sb   = b_skip[lane];
    float tapc = queues[((size_t)b * CH + lane) * TQ + (TQ - 1)];

    if (lane < 25) {
        float v;
        if (lane == 0)      v = x[b];
        else if (lane < 9)  v = num[b * 8 + (lane - 1)];
        else                v = emb[cat[b] * 16 + (lane - 9)];
        s_g[lane] = v;
    }
    __syncwarp();
    float cur = b_in[lane];
#pragma unroll
    for (int k = 0; k < 25; k++)
        cur += W_in[lane * 25 + k] * s_g[k];
    __syncwarp();

    float acc0 = 0.f, acc1 = 0.f, acc2 = 0.f, acc3 = 0.f;

#pragma unroll 1
    for (int i = 0; i < NBLK; i++) {
        const int alpha = i & 1;

        cpa_wait0();
        __syncthreads();   // buffer alpha filled & visible; prev buffer free

        // ---- issue next block's weights into the other buffer -------------
        if (i < NBLK - 1)
            issue_stage(i + 1, alpha ^ 1);

        // ---- prefetch next block's biases + dilated tap (registers) -------
        float zb0n, zb1n, rbn, sbn, tapn;
        if (i < NBLK - 1) {
            const int in = i + 1;
            zb0n = b_conv[in * 64 + lane];
            zb1n = b_conv[in * 64 + 32 + lane];
            rbn  = b_res [in * 32 + lane];
            sbn  = b_skip[in * 32 + lane];
            const int dn = 1 << (in & 7);
            tapn = queues[((size_t)(in * BATCH + b) * CH + lane) * TQ + (TQ - dn)];
        }

        // ---- compute block i ----------------------------------------------
        const size_t rowbase = (size_t)(i * BATCH + b) * CH + lane;
        nq[rowbase * TQO + TQ] = cur;
        s_tap[lane] = tapc;
        s_cur[lane] = cur;
        __syncwarp();

        const float* wc  = sm + WC_OFF  + alpha * 4096;
        const float* wrs = sm + WRS_OFF + alpha * 1024;
        const float* wsk = sm + WSK_OFF + alpha * 1024;
        const float* wo1 = sm + WO1_OFF + alpha * 4096;

        float z0a = zb0, z0b = 0.f, z1a = zb1, z1b = 0.f;
#pragma unroll
        for (int q = 0; q < 8; q++) {            // c = 4q .. 4q+3
            const float4 a  = *(const float4*)&s_tap[4 * q];
            const float4 u  = *(const float4*)&s_cur[4 * q];
            const float4 f00 = *(const float4*)&wc[SWZ16(lane,      2 * q    )];
            const float4 f01 = *(const float4*)&wc[SWZ16(lane,      2 * q + 1)];
            const float4 f10 = *(const float4*)&wc[SWZ16(lane + 32, 2 * q    )];
            const float4 f11 = *(const float4*)&wc[SWZ16(lane + 32, 2 * q + 1)];
            // f.x=W[o][c][0], f.y=W[o][c][1], f.z=W[o][c+1][0], f.w=W[o][c+1][1]
            z0a += a.x * f00.x + a.y * f00.z;
            z0b += u.x * f00.y + u.y * f00.w;
            z0a += a.z * f01.x + a.w * f01.z;
            z0b += u.z * f01.y + u.w * f01.w;
            z1a += a.x * f10.x + a.y * f10.z;
            z1b += u.x * f10.y + u.y * f10.w;
            z1a += a.z * f11.x + a.w * f11.z;
            z1b += u.z * f11.y + u.w * f11.w;
        }

        const float z1s = z1a + z1b;
        const float gated = tanhf(z0a + z0b) * (1.f / (1.f + __expf(-z1s)));
        s_g[lane] = gated;
        __syncwarp();

        float sk = sb, rs = rb;
#pragma unroll
        for (int q = 0; q < 8; q++) {
            const float4 g  = *(const float4*)&s_g[4 * q];
            const float4 wr = *(const float4*)&wrs[SWZ8(lane, q)];
            const float4 ws = *(const float4*)&wsk[SWZ8(lane, q)];
            rs += g.x * wr.x + g.y * wr.y + g.z * wr.z + g.w * wr.w;
            sk += g.x * ws.x + g.y * ws.y + g.z * ws.z + g.w * ws.w;
        }
        cur = rs + cur;

        s_tap[lane] = fmaxf(sk, 0.f);
        __syncwarp();

#pragma unroll
        for (int q = 0; q < 8; q++) {
            const float4 sr = *(const float4*)&s_tap[4 * q];
            const float4 v0 = *(const float4*)&wo1[SWZ8(lane,      q)];
            const float4 v1 = *(const float4*)&wo1[SWZ8(lane + 32, q)];
            const float4 v2 = *(const float4*)&wo1[SWZ8(lane + 64, q)];
            const float4 v3 = *(const float4*)&wo1[SWZ8(lane + 96, q)];
            acc0 += sr.x * v0.x + sr.y * v0.y + sr.z * v0.z + sr.w * v0.w;
            acc1 += sr.x * v1.x + sr.y * v1.y + sr.z * v1.z + sr.w * v1.w;
            acc2 += sr.x * v2.x + sr.y * v2.y + sr.z * v2.z + sr.w * v2.w;
            acc3 += sr.x * v3.x + sr.y * v3.y + sr.z * v3.z + sr.w * v3.w;
        }

        if (i < NBLK - 1) {
            zb0 = zb0n; zb1 = zb1n; rb = rbn; sb = sbn; tapc = tapn;
        }
        __syncthreads();  // everyone done reading buffer alpha before reuse
    }

    // ---- output head -------------------------------------------------------
    float p = 0.f;
    p += fmaxf(acc0 + b_o1[lane      ], 0.f) * W_o2[lane      ];
    p += fmaxf(acc1 + b_o1[lane + 32 ], 0.f) * W_o2[lane + 32 ];
    p += fmaxf(acc2 + b_o1[lane + 64 ], 0.f) * W_o2[lane + 64 ];
    p += fmaxf(acc3 + b_o1[lane + 96 ], 0.f) * W_o2[lane + 96 ];
#pragma unroll
    for (int off = 16; off; off >>= 1)
        p += __shfl_xor_sync(0xffffffffu, p, off);
    if (lane == 0)
        out[b] = p + b_o2[0];
}

extern "C" void kernel_launch(void* const* d_in, const int* in_sizes, int n_in,
                              void* d_out, int out_size) {
    const float* queues = (const float*)d_in[0];
    const float* x      = (const float*)d_in[1];
    const float* num    = (const float*)d_in[2];
    const int*   cat    = (const int*)  d_in[3];
    const float* emb    = (const float*)d_in[4];
    const float* W_in   = (const float*)d_in[5];
    const float* b_in   = (const float*)d_in[6];
    const float* W_conv = (const float*)d_in[7];
    const float* b_conv = (const float*)d_in[8];
    const float* W_res  = (const float*)d_in[9];
    const float* b_res  = (const float*)d_in[10];
    const float* W_skip = (const float*)d_in[11];
    const float* b_skip = (const float*)d_in[12];
    const float* W_o1   = (const float*)d_in[13];
    const float* b_o1   = (const float*)d_in[14];
    const float* W_o2   = (const float*)d_in[15];
    const float* b_o2   = (const float*)d_in[16];
    float* out = (float*)d_out;
    float* nq  = out + BATCH;

    static cudaStream_t s2 = nullptr;
    static cudaEvent_t  e_fork = nullptr, e_join = nullptr;
    if (s2 == nullptr) {
        cudaStreamCreateWithFlags(&s2, cudaStreamNonBlocking);
        cudaEventCreateWithFlags(&e_fork, cudaEventDisableTiming);
        cudaEventCreateWithFlags(&e_join, cudaEventDisableTiming);
        cudaFuncSetAttribute(wave_compute_kernel,
                             cudaFuncAttributeMaxDynamicSharedMemorySize,
                             SMEM_BYTES);
    }

    cudaEventRecord(e_fork, 0);
    cudaStreamWaitEvent(s2, e_fork, 0);

    queue_copy_kernel<<<COPY_CTAS, COPY_TPB, 0, s2>>>(queues, nq);

    wave_compute_kernel<<<CMP_CTAS, CMP_TPB, SMEM_BYTES>>>(
        queues, x, num, cat, emb, W_in, b_in, W_conv, b_conv,
        W_res, b_res, W_skip, b_skip, W_o1, b_o1, W_o2, b_o2, out);

    cudaEventRecord(e_join, s2);
    cudaStreamWaitEvent(0, e_join, 0);
}